// round 10
// baseline (speedup 1.0000x reference)
#include <cuda_runtime.h>
#include <cuda_bf16.h>
#include <cstdint>

// Problem constants (fixed by setup_inputs)
#define NB 16      // batch
#define LL 512     // sequence length
#define DD 256     // encoder dim = filter size
#define TT 4096    // WVF_max_length
#define TP 32      // L-positions per conv block (16 Winograd F(2,3) groups)
#define NG 16      // groups per block

// Intermediates (no cudaMalloc allowed) — referenced directly from device code.
__device__ float g_h1[NB * LL * DD];
__device__ int   g_dur[NB * LL];
__device__ int   g_lmap[NB * TT];
// Winograd-transformed, pair-packed weights per layer:
//   gp[d*256+f]          = (g0,g1) packed   (g0=w0, g1=(w0+w1+w2)/2)
//   gp[65536 + d*256+f]  = (g2,g3) packed   (g2=(w0-w1+w2)/2, g3=w2)
// f fastest -> LDG.64 with 8B lane stride, fully coalesced.
__device__ unsigned long long g_gp1[2 * DD * 256];
__device__ unsigned long long g_gp2[2 * DD * 256];

// ---- packed fp32x2 helpers (sm_100a; ptxas never auto-emits FFMA2) ----
__device__ __forceinline__ void fma2(unsigned long long& acc,
                                     unsigned long long a,
                                     unsigned long long b)
{
    asm("fma.rn.f32x2 %0, %1, %2, %0;" : "+l"(acc) : "l"(a), "l"(b));
}
__device__ __forceinline__ unsigned long long pack2(float a, float b)
{
    unsigned long long r;
    asm("mov.b64 %0, {%1, %2};" : "=l"(r) : "f"(a), "f"(b));
    return r;
}
__device__ __forceinline__ float2 unpack2(unsigned long long v)
{
    float2 r;
    asm("mov.b64 {%0, %1}, %2;" : "=f"(r.x), "=f"(r.y) : "l"(v));
    return r;
}

// ---------------------------------------------------------------------------
// Weight transform + pack: w[k][d][f] -> Winograd g components, pair-packed.
// grid 512 = layer*256 + d, 256 threads (one per f).
// ---------------------------------------------------------------------------
__global__ void __launch_bounds__(256) pack_w_kernel(
    const float* __restrict__ w1, const float* __restrict__ w2)
{
    const int b = blockIdx.x;
    const int layer = b >> 8;
    const int d = b & 255;
    const int f = threadIdx.x;
    const float* src = (layer == 0) ? w1 : w2;
    unsigned long long* dst = (layer == 0) ? g_gp1 : g_gp2;
    const float w0 = src[0 * (DD * 256) + d * 256 + f];
    const float wm = src[1 * (DD * 256) + d * 256 + f];
    const float w2v = src[2 * (DD * 256) + d * 256 + f];
    const float s = 0.5f * (w0 + w2v);
    dst[d * 256 + f]              = pack2(w0, s + 0.5f * wm);       // (g0, g1)
    dst[DD * 256 + d * 256 + f]   = pack2(s - 0.5f * wm, w2v);      // (g2, g3)
}

// ---------------------------------------------------------------------------
// Fused Winograd-F(2,3) conv1d(K=3, same pad) + bias + LayerNorm(F) + ReLU
// STAGE 0: src = x, gp = g_gp1, writes h to g_h1.
// STAGE 1: src = g_h1, gp = g_gp2, fuses the final linear + duration:
//          dur[n,l] = int(relu(h.lin_w + lin_b) + 0.5) — h2 never hits gmem.
// One block = 32 L-positions = 16 groups, 256 threads (one per channel f).
// Dynamic smem (100352 B): zp0[16][256] ull | zp1[16][256] ull | xs[34][256] f32
// xs region reused as the LN tile after the transform.
// ---------------------------------------------------------------------------
#define SMEM_BYTES (2 * NG * DD * 8 + (TP + 2) * DD * 4)   // 65536 + 34816

template<int STAGE>
__global__ void __launch_bounds__(256, 2) conv_ln_relu_kernel(
    const float* __restrict__ x,
    const float* __restrict__ bias,
    const float* __restrict__ gamma,
    const float* __restrict__ beta,
    const float* __restrict__ lin_w,
    const float* __restrict__ lin_b)
{
    extern __shared__ char smem_raw[];
    unsigned long long* zp0 = (unsigned long long*)smem_raw;            // [NG][256]
    unsigned long long* zp1 = zp0 + NG * DD;                            // [NG][256]
    float (*xs)[DD] = (float(*)[DD])(smem_raw + 2 * NG * DD * 8);       // [34][256]
    __shared__ float mu_s[TP];
    __shared__ float rs_s[TP];

    const float* __restrict__ src = (STAGE == 0) ? x : (const float*)g_h1;
    const unsigned long long* __restrict__ gp =
        (STAGE == 0) ? (const unsigned long long*)g_gp1
                     : (const unsigned long long*)g_gp2;

    const int blk = blockIdx.x;
    const int n   = blk / (LL / TP);
    const int l0  = (blk % (LL / TP)) * TP;
    const int f   = threadIdx.x;

    // Load input rows (zero padding at sequence edges)
    #pragma unroll
    for (int r = 0; r < TP + 2; r++) {
        int l = l0 - 1 + r;
        xs[r][f] = (l >= 0 && l < LL) ? src[(n * LL + l) * DD + f] : 0.f;
    }
    __syncthreads();

    // Winograd input transform per group g (outputs p=2g, 2g+1):
    // x0..x3 = xs[2g..2g+3];  zp0=(x0-x2, x1+x2), zp1=(x2-x1, x1-x3)
    #pragma unroll
    for (int g = 0; g < NG; g++) {
        const float x0 = xs[2 * g + 0][f];
        const float x1 = xs[2 * g + 1][f];
        const float x2 = xs[2 * g + 2][f];
        const float x3 = xs[2 * g + 3][f];
        zp0[g * DD + f] = pack2(x0 - x2, x1 + x2);
        zp1[g * DD + f] = pack2(x2 - x1, x1 - x3);
    }
    __syncthreads();

    // m01[g] = (Σ_d z0*g0, Σ_d z1*g1);  m23[g] = (Σ_d z2*g2, Σ_d z3*g3)
    unsigned long long m01[NG], m23[NG];
    #pragma unroll
    for (int g = 0; g < NG; g++) { m01[g] = 0ull; m23[g] = 0ull; }

    const unsigned long long* gp01 = gp + f;
    const unsigned long long* gp23 = gp + DD * 256 + f;

    // Mainloop: d in steps of 4.
    // Per step: 8 coalesced LDG.64 (weights), 64 LDS.128 (broadcast), 128 FFMA2.
    #pragma unroll 1
    for (int d = 0; d < DD; d += 4) {
        unsigned long long w01[4], w23[4];
        #pragma unroll
        for (int j = 0; j < 4; j++) {
            w01[j] = gp01[(d + j) * 256];
            w23[j] = gp23[(d + j) * 256];
        }
        #pragma unroll
        for (int g = 0; g < NG; g++) {
            const ulonglong2 a0 = *(const ulonglong2*)&zp0[g * DD + d];
            const ulonglong2 a1 = *(const ulonglong2*)&zp0[g * DD + d + 2];
            const ulonglong2 b0 = *(const ulonglong2*)&zp1[g * DD + d];
            const ulonglong2 b1 = *(const ulonglong2*)&zp1[g * DD + d + 2];
            fma2(m01[g], a0.x, w01[0]);
            fma2(m01[g], a0.y, w01[1]);
            fma2(m01[g], a1.x, w01[2]);
            fma2(m01[g], a1.y, w01[3]);
            fma2(m23[g], b0.x, w23[0]);
            fma2(m23[g], b0.y, w23[1]);
            fma2(m23[g], b1.x, w23[2]);
            fma2(m23[g], b1.y, w23[3]);
        }
    }
    __syncthreads();   // zp/xs reads done; reuse xs region as the h tile

    float (*hs)[DD] = xs;

    // Inverse transform + bias: y0 = m0+m1+m2, y1 = m1-m2-m3
    float acc[TP];
    {
        const float bf = bias[f];
        #pragma unroll
        for (int g = 0; g < NG; g++) {
            const float2 u = unpack2(m01[g]);
            const float2 v = unpack2(m23[g]);
            acc[2 * g + 0] = u.x + u.y + v.x + bf;
            acc[2 * g + 1] = u.y - v.x - v.y + bf;
            hs[2 * g + 0][f] = acc[2 * g + 0];
            hs[2 * g + 1][f] = acc[2 * g + 1];
        }
    }
    __syncthreads();

    // LayerNorm over f (256) per position p: warp-parallel reductions
    {
        const int wid = f >> 5, lane = f & 31;
        #pragma unroll
        for (int rr = 0; rr < 4; rr++) {
            int r = wid * 4 + rr;
            float s = 0.f, s2 = 0.f;
            #pragma unroll
            for (int c0 = 0; c0 < 256; c0 += 32) {
                float v = hs[r][c0 + lane];
                s += v; s2 += v * v;
            }
            #pragma unroll
            for (int o = 16; o; o >>= 1) {
                s  += __shfl_xor_sync(0xFFFFFFFFu, s,  o);
                s2 += __shfl_xor_sync(0xFFFFFFFFu, s2, o);
            }
            if (lane == 0) {
                float mu = s * (1.f / 256.f);
                float var = s2 * (1.f / 256.f) - mu * mu;
                mu_s[r] = mu;
                rs_s[r] = rsqrtf(var + 1e-5f);
            }
        }
    }
    __syncthreads();

    if (STAGE == 0) {
        const float gg = gamma[f], bb = beta[f];
        #pragma unroll
        for (int p = 0; p < TP; p++) {
            float v = (acc[p] - mu_s[p]) * rs_s[p] * gg + bb;
            g_h1[(n * LL + l0 + p) * 256 + f] = fmaxf(v, 0.f);
        }
    } else {
        // Fused linear head: prod[p][f] = relu(LN(h)) * lin_w[f], reduce over f.
        const float gg = gamma[f], bb = beta[f];
        const float lw = lin_w[f];
        #pragma unroll
        for (int p = 0; p < TP; p++) {
            float v = fmaxf((acc[p] - mu_s[p]) * rs_s[p] * gg + bb, 0.f);
            hs[p][f] = v * lw;
        }
        __syncthreads();
        {
            const int wid = f >> 5, lane = f & 31;
            const float lb = lin_b[0];
            #pragma unroll
            for (int rr = 0; rr < 4; rr++) {
                int r = wid * 4 + rr;
                float s = 0.f;
                #pragma unroll
                for (int c0 = 0; c0 < 256; c0 += 32)
                    s += hs[r][c0 + lane];
                #pragma unroll
                for (int o = 16; o; o >>= 1)
                    s += __shfl_xor_sync(0xFFFFFFFFu, s, o);
                if (lane == 0) {
                    float dpo = fmaxf(s + lb, 0.f);
                    g_dur[n * LL + l0 + r] = (int)(dpo + 0.5f);
                }
            }
        }
    }
}

// ---------------------------------------------------------------------------
// Inclusive scan of durations per row + t -> l binary-search map.
// ---------------------------------------------------------------------------
__global__ void __launch_bounds__(512) scan_map_kernel()
{
    const int n = blockIdx.x;
    const int l = threadIdx.x;

    __shared__ int sc[LL];
    sc[l] = g_dur[n * LL + l];
    __syncthreads();
    for (int off = 1; off < LL; off <<= 1) {
        int v = (l >= off) ? sc[l - off] : 0;
        __syncthreads();
        sc[l] += v;
        __syncthreads();
    }

    const int total = sc[LL - 1];
    for (int t = l; t < TT; t += LL) {
        int res = -1;
        if (t < total) {
            int lo = 0, hi = LL - 1;
            while (lo < hi) {
                int mid = (lo + hi) >> 1;
                if (sc[mid] > t) hi = mid; else lo = mid + 1;
            }
            res = lo;
        }
        g_lmap[n * TT + t] = res;
    }
}

// ---------------------------------------------------------------------------
// out[n, t, :] = x[n, lmap[n,t], :]  (or zeros). float4 streaming copy.
// ---------------------------------------------------------------------------
__global__ void __launch_bounds__(256) expand_copy_kernel(
    const float* __restrict__ x,
    float* __restrict__ out)
{
    const int idx = blockIdx.x * blockDim.x + threadIdx.x;  // over NB*TT*64 float4
    const int c = idx & 63;
    const int t = (idx >> 6) & (TT - 1);
    const int n = idx >> 18;
    const int l = g_lmap[n * TT + t];
    float4 v = make_float4(0.f, 0.f, 0.f, 0.f);
    if (l >= 0) v = ((const float4*)x)[(n * LL + l) * (DD / 4) + c];
    ((float4*)out)[idx] = v;
}

// ---------------------------------------------------------------------------
// Optional second output: WVF_pos = 1..TT (if the harness concatenated it)
// ---------------------------------------------------------------------------
__global__ void tail_kernel(float* __restrict__ out, int tail)
{
    int i = blockIdx.x * blockDim.x + threadIdx.x;
    if (i < tail) out[NB * TT * DD + i] = (float)((i % TT) + 1);
}

extern "C" void kernel_launch(void* const* d_in, const int* in_sizes, int n_in,
                              void* d_out, int out_size)
{
    const float* x       = (const float*)d_in[0];
    const float* conv1_w = (const float*)d_in[1];
    const float* conv1_b = (const float*)d_in[2];
    const float* ln1_g   = (const float*)d_in[3];
    const float* ln1_b   = (const float*)d_in[4];
    const float* conv2_w = (const float*)d_in[5];
    const float* conv2_b = (const float*)d_in[6];
    const float* ln2_g   = (const float*)d_in[7];
    const float* ln2_b   = (const float*)d_in[8];
    const float* lin_w   = (const float*)d_in[9];
    const float* lin_b   = (const float*)d_in[10];

    float* out = (float*)d_out;

    // Opt-in to >48KB dynamic smem (idempotent; not an allocation; capture-safe).
    static bool attr_done = false;
    if (!attr_done) {
        cudaFuncSetAttribute(conv_ln_relu_kernel<0>,
                             cudaFuncAttributeMaxDynamicSharedMemorySize, SMEM_BYTES);
        cudaFuncSetAttribute(conv_ln_relu_kernel<1>,
                             cudaFuncAttributeMaxDynamicSharedMemorySize, SMEM_BYTES);
        attr_done = true;
    }

    pack_w_kernel<<<2 * DD, 256>>>(conv1_w, conv2_w);

    const int conv_grid = NB * (LL / TP);   // 256
    conv_ln_relu_kernel<0><<<conv_grid, 256, SMEM_BYTES>>>(x, conv1_b, ln1_g, ln1_b, lin_w, lin_b);
    conv_ln_relu_kernel<1><<<conv_grid, 256, SMEM_BYTES>>>(x, conv2_b, ln2_g, ln2_b, lin_w, lin_b);
    scan_map_kernel<<<NB, LL>>>();

    const int n_f4 = NB * TT * (DD / 4);    // 4,194,304
    expand_copy_kernel<<<n_f4 / 256, 256>>>(x, out);

    const int main_elems = NB * TT * DD;
    int tail = out_size - main_elems;
    if (tail > 0) {
        tail_kernel<<<(tail + 255) / 256, 256>>>(out, tail);
    }
}

// round 11
// speedup vs baseline: 1.1010x; 1.1010x over previous
#include <cuda_runtime.h>
#include <cuda_bf16.h>
#include <cstdint>

// Problem constants (fixed by setup_inputs)
#define NB 16      // batch
#define LL 512     // sequence length
#define DD 256     // encoder dim = filter size
#define TT 4096    // WVF_max_length
#define TP 32      // L-positions per conv block

// Intermediates (no cudaMalloc allowed) — referenced directly from device code.
__device__ float g_h1[NB * LL * DD];
__device__ int   g_dur[NB * LL];
__device__ int   g_lmap[NB * TT];
// Pair-packed weights: wp[kk][d2][f] = (w[kk][2*d2][f], w[kk][2*d2+1][f]) as b64.
// f stays the fastest axis -> LDG.64 with 8B lane stride, fully coalesced.
__device__ unsigned long long g_wp1[3 * (DD / 2) * 256];
__device__ unsigned long long g_wp2[3 * (DD / 2) * 256];

// ---- packed fp32x2 helpers (sm_100a; ptxas never auto-emits FFMA2) ----
__device__ __forceinline__ void fma2(unsigned long long& acc,
                                     unsigned long long a,
                                     unsigned long long b)
{
    asm("fma.rn.f32x2 %0, %1, %2, %0;" : "+l"(acc) : "l"(a), "l"(b));
}
__device__ __forceinline__ unsigned long long pack2(float a, float b)
{
    unsigned long long r;
    asm("mov.b64 %0, {%1, %2};" : "=l"(r) : "f"(a), "f"(b));
    return r;
}
__device__ __forceinline__ float2 unpack2(unsigned long long v)
{
    float2 r;
    asm("mov.b64 {%0, %1}, %2;" : "=f"(r.x), "=f"(r.y) : "l"(v));
    return r;
}

// ---------------------------------------------------------------------------
// Weight pair-packing: w[kk][d][f] -> wp[kk][d/2][f] (b64 of two d-adjacent
// values). Reads and writes both coalesced along f.
// ---------------------------------------------------------------------------
__global__ void __launch_bounds__(256) pack_w_kernel(
    const float* __restrict__ w1, const float* __restrict__ w2)
{
    const int b = blockIdx.x;           // 0..767: tensor*384 + kk*128 + d2
    const int tensor = b / 384;
    const int kk = (b % 384) / 128;
    const int d2 = b % 128;
    const int f  = threadIdx.x;
    const float* src = (tensor == 0) ? w1 : w2;
    unsigned long long* dst = (tensor == 0) ? g_wp1 : g_wp2;
    const float a = src[kk * (DD * 256) + (2 * d2)     * 256 + f];
    const float c = src[kk * (DD * 256) + (2 * d2 + 1) * 256 + f];
    dst[kk * ((DD / 2) * 256) + d2 * 256 + f] = pack2(a, c);
}

// ---------------------------------------------------------------------------
// Fused conv1d(K=3, same pad) + bias + LayerNorm(F) + ReLU
// STAGE 0: src = x, wp = g_wp1, writes h to g_h1.
// STAGE 1: src = g_h1, wp = g_wp2, fuses the final linear + duration:
//          dur[n,l] = int(relu(h.lin_w + lin_b) + 0.5) — h2 never hits gmem.
// One block = 32 consecutive L positions, 256 threads (one per output chan f).
// Grid = 256 blocks -> 2 blocks/SM, fully resident in one wave.
// Weight loads are software-pipelined: next d-step's 6 LDG.64 issue before
// the current 192-FFMA2 block, hiding the L2 latency under FMA issue.
// ---------------------------------------------------------------------------
template<int STAGE>
__global__ void __launch_bounds__(256, 2) conv_ln_relu_kernel(
    const float* __restrict__ x,
    const float* __restrict__ bias,
    const float* __restrict__ gamma,
    const float* __restrict__ beta,
    const float* __restrict__ lin_w,
    const float* __restrict__ lin_b)
{
    __shared__ float xs[TP + 2][DD];   // 34.8 KB; reused as LN tile afterwards
    __shared__ float mu_s[TP];
    __shared__ float rs_s[TP];

    const float* __restrict__ src = (STAGE == 0) ? x : (const float*)g_h1;
    const unsigned long long* __restrict__ wp =
        (STAGE == 0) ? (const unsigned long long*)g_wp1
                     : (const unsigned long long*)g_wp2;

    const int blk = blockIdx.x;
    const int n   = blk / (LL / TP);
    const int l0  = (blk % (LL / TP)) * TP;
    const int f   = threadIdx.x;

    // Load input rows (zero padding at sequence edges)
    #pragma unroll
    for (int r = 0; r < TP + 2; r++) {
        int l = l0 - 1 + r;
        xs[r][f] = (l >= 0 && l < LL) ? src[(n * LL + l) * DD + f] : 0.f;
    }
    __syncthreads();

    // acc2[p] = (sum over even d, sum over odd d) packed fp32x2  (64 regs)
    unsigned long long acc2[TP];
    #pragma unroll
    for (int p = 0; p < TP; p++) acc2[p] = 0ull;

    const unsigned long long* wf0 = wp + f;                         // kk = 0
    const unsigned long long* wf1 = wp + (DD / 2) * 256 + f;        // kk = 1
    const unsigned long long* wf2 = wp + 2 * (DD / 2) * 256 + f;    // kk = 2

    // Prologue: load d-step 0's weights
    unsigned long long c01[3], c23[3];
    c01[0] = wf0[0];        c23[0] = wf0[256];
    c01[1] = wf1[0];        c23[1] = wf1[256];
    c01[2] = wf2[0];        c23[2] = wf2[256];

    // Mainloop: d in steps of 4 (= 2 packed pairs), software-pipelined weights.
    // Per step: 6 prefetch LDG.64, 34 LDS.128 (broadcast), 192 FFMA2.
    #pragma unroll 1
    for (int d2 = 0; d2 < DD / 2; d2 += 2) {
        // Prefetch next step (clamped at the end; result unused there)
        const int dn = (d2 + 2 < DD / 2) ? d2 + 2 : 0;
        unsigned long long n01[3], n23[3];
        n01[0] = wf0[dn * 256];  n23[0] = wf0[(dn + 1) * 256];
        n01[1] = wf1[dn * 256];  n23[1] = wf1[(dn + 1) * 256];
        n01[2] = wf2[dn * 256];  n23[2] = wf2[(dn + 1) * 256];

        #pragma unroll
        for (int r = 0; r < TP + 2; r++) {
            // one LDS.128 -> two aligned b64 operands (broadcast across lanes)
            const ulonglong2 xv = *(const ulonglong2*)&xs[r][d2 * 2];
            #pragma unroll
            for (int kk = 0; kk < 3; kk++) {
                const int p = r - kk;      // output position using row r at tap kk
                if (p >= 0 && p < TP) {    // compile-time after unroll
                    fma2(acc2[p], xv.x, c01[kk]);
                    fma2(acc2[p], xv.y, c23[kk]);
                }
            }
        }

        #pragma unroll
        for (int kk = 0; kk < 3; kk++) { c01[kk] = n01[kk]; c23[kk] = n23[kk]; }
    }
    __syncthreads();   // all xs reads done; reuse xs as the h tile

    float (*hs)[DD] = xs;   // alias first TP rows

    // Horizontal combine + bias; stage into hs for LayerNorm stats
    float acc[TP];
    {
        const float bf = bias[f];
        #pragma unroll
        for (int p = 0; p < TP; p++) {
            float2 v = unpack2(acc2[p]);
            acc[p] = v.x + v.y + bf;
            hs[p][f] = acc[p];
        }
    }
    __syncthreads();

    // LayerNorm over f (256) per position p: warp-parallel reductions
    {
        const int wid = f >> 5, lane = f & 31;
        #pragma unroll
        for (int rr = 0; rr < 4; rr++) {
            int r = wid * 4 + rr;
            float s = 0.f, s2 = 0.f;
            #pragma unroll
            for (int c0 = 0; c0 < 256; c0 += 32) {
                float v = hs[r][c0 + lane];
                s += v; s2 += v * v;
            }
            #pragma unroll
            for (int o = 16; o; o >>= 1) {
                s  += __shfl_xor_sync(0xFFFFFFFFu, s,  o);
                s2 += __shfl_xor_sync(0xFFFFFFFFu, s2, o);
            }
            if (lane == 0) {
                float mu = s * (1.f / 256.f);
                float var = s2 * (1.f / 256.f) - mu * mu;
                mu_s[r] = mu;
                rs_s[r] = rsqrtf(var + 1e-5f);
            }
        }
    }
    __syncthreads();

    if (STAGE == 0) {
        const float gg = gamma[f], bb = beta[f];
        #pragma unroll
        for (int p = 0; p < TP; p++) {
            float v = (acc[p] - mu_s[p]) * rs_s[p] * gg + bb;
            g_h1[(n * LL + l0 + p) * 256 + f] = fmaxf(v, 0.f);
        }
    } else {
        // Fused linear head: prod[p][f] = relu(LN(h)) * lin_w[f], reduce over f.
        const float gg = gamma[f], bb = beta[f];
        const float lw = lin_w[f];
        #pragma unroll
        for (int p = 0; p < TP; p++) {
            float v = fmaxf((acc[p] - mu_s[p]) * rs_s[p] * gg + bb, 0.f);
            hs[p][f] = v * lw;
        }
        __syncthreads();
        {
            const int wid = f >> 5, lane = f & 31;
            const float lb = lin_b[0];
            #pragma unroll
            for (int rr = 0; rr < 4; rr++) {
                int r = wid * 4 + rr;
                float s = 0.f;
                #pragma unroll
                for (int c0 = 0; c0 < 256; c0 += 32)
                    s += hs[r][c0 + lane];
                #pragma unroll
                for (int o = 16; o; o >>= 1)
                    s += __shfl_xor_sync(0xFFFFFFFFu, s, o);
                if (lane == 0) {
                    float dpo = fmaxf(s + lb, 0.f);
                    g_dur[n * LL + l0 + r] = (int)(dpo + 0.5f);
                }
            }
        }
    }
}

// ---------------------------------------------------------------------------
// Inclusive scan of durations per row + t -> l binary-search map.
// ---------------------------------------------------------------------------
__global__ void __launch_bounds__(512) scan_map_kernel()
{
    const int n = blockIdx.x;
    const int l = threadIdx.x;

    __shared__ int sc[LL];
    sc[l] = g_dur[n * LL + l];
    __syncthreads();
    for (int off = 1; off < LL; off <<= 1) {
        int v = (l >= off) ? sc[l - off] : 0;
        __syncthreads();
        sc[l] += v;
        __syncthreads();
    }

    const int total = sc[LL - 1];
    for (int t = l; t < TT; t += LL) {
        int res = -1;
        if (t < total) {
            int lo = 0, hi = LL - 1;
            while (lo < hi) {
                int mid = (lo + hi) >> 1;
                if (sc[mid] > t) hi = mid; else lo = mid + 1;
            }
            res = lo;
        }
        g_lmap[n * TT + t] = res;
    }
}

// ---------------------------------------------------------------------------
// out[n, t, :] = x[n, lmap[n,t], :]  (or zeros). float4 streaming copy.
// ---------------------------------------------------------------------------
__global__ void __launch_bounds__(256) expand_copy_kernel(
    const float* __restrict__ x,
    float* __restrict__ out)
{
    const int idx = blockIdx.x * blockDim.x + threadIdx.x;  // over NB*TT*64 float4
    const int c = idx & 63;
    const int t = (idx >> 6) & (TT - 1);
    const int n = idx >> 18;
    const int l = g_lmap[n * TT + t];
    float4 v = make_float4(0.f, 0.f, 0.f, 0.f);
    if (l >= 0) v = ((const float4*)x)[(n * LL + l) * (DD / 4) + c];
    ((float4*)out)[idx] = v;
}

// ---------------------------------------------------------------------------
// Optional second output: WVF_pos = 1..TT (if the harness concatenated it)
// ---------------------------------------------------------------------------
__global__ void tail_kernel(float* __restrict__ out, int tail)
{
    int i = blockIdx.x * blockDim.x + threadIdx.x;
    if (i < tail) out[NB * TT * DD + i] = (float)((i % TT) + 1);
}

extern "C" void kernel_launch(void* const* d_in, const int* in_sizes, int n_in,
                              void* d_out, int out_size)
{
    const float* x       = (const float*)d_in[0];
    const float* conv1_w = (const float*)d_in[1];
    const float* conv1_b = (const float*)d_in[2];
    const float* ln1_g   = (const float*)d_in[3];
    const float* ln1_b   = (const float*)d_in[4];
    const float* conv2_w = (const float*)d_in[5];
    const float* conv2_b = (const float*)d_in[6];
    const float* ln2_g   = (const float*)d_in[7];
    const float* ln2_b   = (const float*)d_in[8];
    const float* lin_w   = (const float*)d_in[9];
    const float* lin_b   = (const float*)d_in[10];

    float* out = (float*)d_out;

    // Pure kernel launches only — fully graph-capturable.
    pack_w_kernel<<<2 * 3 * (DD / 2), 256>>>(conv1_w, conv2_w);

    const int conv_grid = NB * (LL / TP);   // 256
    conv_ln_relu_kernel<0><<<conv_grid, 256>>>(x, conv1_b, ln1_g, ln1_b, lin_w, lin_b);
    conv_ln_relu_kernel<1><<<conv_grid, 256>>>(x, conv2_b, ln2_g, ln2_b, lin_w, lin_b);
    scan_map_kernel<<<NB, LL>>>();

    const int n_f4 = NB * TT * (DD / 4);    // 4,194,304
    expand_copy_kernel<<<n_f4 / 256, 256>>>(x, out);

    const int main_elems = NB * TT * DD;
    int tail = out_size - main_elems;
    if (tail > 0) {
        tail_kernel<<<(tail + 255) / 256, 256>>>(out, tail);
    }
}

// round 12
// speedup vs baseline: 1.1504x; 1.0449x over previous
#include <cuda_runtime.h>
#include <cuda_bf16.h>
#include <cstdint>

// Problem constants (fixed by setup_inputs)
#define NB 16      // batch
#define LL 512     // sequence length
#define DD 256     // encoder dim = filter size
#define TT 4096    // WVF_max_length
#define TP 32      // L-positions per conv block

// Intermediates (no cudaMalloc allowed) — referenced directly from device code.
__device__ float g_h1[NB * LL * DD];
__device__ int   g_dur[NB * LL];
__device__ int   g_lmap[NB * TT];
// Pair-packed weights: wp[kk][d2][f] = (w[kk][2*d2][f], w[kk][2*d2+1][f]) as b64.
// f stays the fastest axis -> LDG.64 with 8B lane stride, fully coalesced.
__device__ unsigned long long g_wp1[3 * (DD / 2) * 256];
__device__ unsigned long long g_wp2[3 * (DD / 2) * 256];

// ---- packed fp32x2 helpers (sm_100a; ptxas never auto-emits FFMA2) ----
__device__ __forceinline__ void fma2(unsigned long long& acc,
                                     unsigned long long a,
                                     unsigned long long b)
{
    asm("fma.rn.f32x2 %0, %1, %2, %0;" : "+l"(acc) : "l"(a), "l"(b));
}
__device__ __forceinline__ unsigned long long pack2(float a, float b)
{
    unsigned long long r;
    asm("mov.b64 %0, {%1, %2};" : "=l"(r) : "f"(a), "f"(b));
    return r;
}
__device__ __forceinline__ float2 unpack2(unsigned long long v)
{
    float2 r;
    asm("mov.b64 {%0, %1}, %2;" : "=f"(r.x), "=f"(r.y) : "l"(v));
    return r;
}

// ---------------------------------------------------------------------------
// Weight pair-packing: w[kk][d][f] -> wp[kk][d/2][f] (b64 of two d-adjacent
// values). Reads and writes both coalesced along f.
// ---------------------------------------------------------------------------
__global__ void __launch_bounds__(256) pack_w_kernel(
    const float* __restrict__ w1, const float* __restrict__ w2)
{
    const int b = blockIdx.x;           // 0..767: tensor*384 + kk*128 + d2
    const int tensor = b / 384;
    const int kk = (b % 384) / 128;
    const int d2 = b % 128;
    const int f  = threadIdx.x;
    const float* src = (tensor == 0) ? w1 : w2;
    unsigned long long* dst = (tensor == 0) ? g_wp1 : g_wp2;
    const float a = src[kk * (DD * 256) + (2 * d2)     * 256 + f];
    const float c = src[kk * (DD * 256) + (2 * d2 + 1) * 256 + f];
    dst[kk * ((DD / 2) * 256) + d2 * 256 + f] = pack2(a, c);
}

// ---------------------------------------------------------------------------
// Fused conv1d(K=3, same pad) + bias + LayerNorm(F) + ReLU  (R9 mainloop)
// STAGE 0: src = x, wp = g_wp1, writes h to g_h1.
// STAGE 1: src = g_h1, wp = g_wp2, fuses the final linear + duration:
//          dur[n,l] = int(relu(h.lin_w + lin_b) + 0.5) — h2 never hits gmem.
// One block = 32 consecutive L positions, 256 threads (one per output chan f).
// ---------------------------------------------------------------------------
template<int STAGE>
__global__ void __launch_bounds__(256, 2) conv_ln_relu_kernel(
    const float* __restrict__ x,
    const float* __restrict__ bias,
    const float* __restrict__ gamma,
    const float* __restrict__ beta,
    const float* __restrict__ lin_w,
    const float* __restrict__ lin_b)
{
    __shared__ float xs[TP + 2][DD];   // 34.8 KB; reused as LN tile afterwards
    __shared__ float mu_s[TP];
    __shared__ float rs_s[TP];

    const float* __restrict__ src = (STAGE == 0) ? x : (const float*)g_h1;
    const unsigned long long* __restrict__ wp =
        (STAGE == 0) ? (const unsigned long long*)g_wp1
                     : (const unsigned long long*)g_wp2;

    const int blk = blockIdx.x;
    const int n   = blk / (LL / TP);
    const int l0  = (blk % (LL / TP)) * TP;
    const int f   = threadIdx.x;

    // Load input rows (zero padding at sequence edges)
    #pragma unroll
    for (int r = 0; r < TP + 2; r++) {
        int l = l0 - 1 + r;
        xs[r][f] = (l >= 0 && l < LL) ? src[(n * LL + l) * DD + f] : 0.f;
    }
    __syncthreads();

    // acc2[p] = (sum over even d, sum over odd d) packed fp32x2  (64 regs)
    unsigned long long acc2[TP];
    #pragma unroll
    for (int p = 0; p < TP; p++) acc2[p] = 0ull;

    const unsigned long long* wf = wp + f;   // this thread's column

    // Mainloop: d in steps of 4 (= 2 packed pairs).
    // Per step: 6 coalesced LDG.64 (weights), 34 LDS.128 (broadcast), 192 FFMA2.
    #pragma unroll 2
    for (int d2 = 0; d2 < DD / 2; d2 += 2) {
        unsigned long long wk01[3], wk23[3];
        #pragma unroll
        for (int kk = 0; kk < 3; kk++) {
            const unsigned long long* wkk = wf + kk * ((DD / 2) * 256);
            wk01[kk] = wkk[d2 * 256];
            wk23[kk] = wkk[(d2 + 1) * 256];
        }
        #pragma unroll
        for (int r = 0; r < TP + 2; r++) {
            // one LDS.128 -> two aligned b64 operands (broadcast across lanes)
            const ulonglong2 xv = *(const ulonglong2*)&xs[r][d2 * 2];
            #pragma unroll
            for (int kk = 0; kk < 3; kk++) {
                const int p = r - kk;      // output position using row r at tap kk
                if (p >= 0 && p < TP) {    // compile-time after unroll
                    fma2(acc2[p], xv.x, wk01[kk]);
                    fma2(acc2[p], xv.y, wk23[kk]);
                }
            }
        }
    }
    __syncthreads();   // all xs reads done; reuse xs as the h tile

    float (*hs)[DD] = xs;   // alias first TP rows

    // Horizontal combine + bias; stage into hs for LayerNorm stats
    float acc[TP];
    {
        const float bf = bias[f];
        #pragma unroll
        for (int p = 0; p < TP; p++) {
            float2 v = unpack2(acc2[p]);
            acc[p] = v.x + v.y + bf;
            hs[p][f] = acc[p];
        }
    }
    __syncthreads();

    // LayerNorm over f (256) per position p: warp-parallel reductions
    {
        const int wid = f >> 5, lane = f & 31;
        #pragma unroll
        for (int rr = 0; rr < 4; rr++) {
            int r = wid * 4 + rr;
            float s = 0.f, s2 = 0.f;
            #pragma unroll
            for (int c0 = 0; c0 < 256; c0 += 32) {
                float v = hs[r][c0 + lane];
                s += v; s2 += v * v;
            }
            #pragma unroll
            for (int o = 16; o; o >>= 1) {
                s  += __shfl_xor_sync(0xFFFFFFFFu, s,  o);
                s2 += __shfl_xor_sync(0xFFFFFFFFu, s2, o);
            }
            if (lane == 0) {
                float mu = s * (1.f / 256.f);
                float var = s2 * (1.f / 256.f) - mu * mu;
                mu_s[r] = mu;
                rs_s[r] = rsqrtf(var + 1e-5f);
            }
        }
    }
    __syncthreads();

    if (STAGE == 0) {
        const float gg = gamma[f], bb = beta[f];
        #pragma unroll
        for (int p = 0; p < TP; p++) {
            float v = (acc[p] - mu_s[p]) * rs_s[p] * gg + bb;
            g_h1[(n * LL + l0 + p) * 256 + f] = fmaxf(v, 0.f);
        }
    } else {
        // Fused linear head: prod[p][f] = relu(LN(h)) * lin_w[f], reduce over f.
        const float gg = gamma[f], bb = beta[f];
        const float lw = lin_w[f];
        #pragma unroll
        for (int p = 0; p < TP; p++) {
            float v = fmaxf((acc[p] - mu_s[p]) * rs_s[p] * gg + bb, 0.f);
            hs[p][f] = v * lw;
        }
        __syncthreads();
        {
            const int wid = f >> 5, lane = f & 31;
            const float lb = lin_b[0];
            #pragma unroll
            for (int rr = 0; rr < 4; rr++) {
                int r = wid * 4 + rr;
                float s = 0.f;
                #pragma unroll
                for (int c0 = 0; c0 < 256; c0 += 32)
                    s += hs[r][c0 + lane];
                #pragma unroll
                for (int o = 16; o; o >>= 1)
                    s += __shfl_xor_sync(0xFFFFFFFFu, s, o);
                if (lane == 0) {
                    float dpo = fmaxf(s + lb, 0.f);
                    g_dur[n * LL + l0 + r] = (int)(dpo + 0.5f);
                }
            }
        }
    }
}

// ---------------------------------------------------------------------------
// Inclusive scan of durations per row + t -> l binary-search map.
// ---------------------------------------------------------------------------
__global__ void __launch_bounds__(512) scan_map_kernel()
{
    const int n = blockIdx.x;
    const int l = threadIdx.x;

    __shared__ int sc[LL];
    sc[l] = g_dur[n * LL + l];
    __syncthreads();
    for (int off = 1; off < LL; off <<= 1) {
        int v = (l >= off) ? sc[l - off] : 0;
        __syncthreads();
        sc[l] += v;
        __syncthreads();
    }

    const int total = sc[LL - 1];
    for (int t = l; t < TT; t += LL) {
        int res = -1;
        if (t < total) {
            int lo = 0, hi = LL - 1;
            while (lo < hi) {
                int mid = (lo + hi) >> 1;
                if (sc[mid] > t) hi = mid; else lo = mid + 1;
            }
            res = lo;
        }
        g_lmap[n * TT + t] = res;
    }
}

// ---------------------------------------------------------------------------
// out[n, t, :] = x[n, lmap[n,t], :]  (or zeros), grid-stride (8 float4/thread)
// + fused tail (WVF_pos = 1..TT) handling. 2048 blocks instead of 16384.
// ---------------------------------------------------------------------------
#define EXP_BLOCKS 2048
__global__ void __launch_bounds__(256) expand_copy_kernel(
    const float* __restrict__ x,
    float* __restrict__ out,
    int tail)
{
    const int nthreads = EXP_BLOCKS * 256;
    const int tid0 = blockIdx.x * 256 + threadIdx.x;

    #pragma unroll
    for (int k = 0; k < 8; k++) {
        const int idx = tid0 + k * nthreads;       // over NB*TT*64 float4
        const int c = idx & 63;
        const int t = (idx >> 6) & (TT - 1);
        const int n = idx >> 18;
        const int l = g_lmap[n * TT + t];
        float4 v = make_float4(0.f, 0.f, 0.f, 0.f);
        if (l >= 0) v = ((const float4*)x)[(n * LL + l) * (DD / 4) + c];
        ((float4*)out)[idx] = v;
    }

    // Fused tail: out[NB*TT*DD + i] = (i % TT) + 1
    for (int i = tid0; i < tail; i += nthreads)
        out[NB * TT * DD + i] = (float)((i % TT) + 1);
}

extern "C" void kernel_launch(void* const* d_in, const int* in_sizes, int n_in,
                              void* d_out, int out_size)
{
    const float* x       = (const float*)d_in[0];
    const float* conv1_w = (const float*)d_in[1];
    const float* conv1_b = (const float*)d_in[2];
    const float* ln1_g   = (const float*)d_in[3];
    const float* ln1_b   = (const float*)d_in[4];
    const float* conv2_w = (const float*)d_in[5];
    const float* conv2_b = (const float*)d_in[6];
    const float* ln2_g   = (const float*)d_in[7];
    const float* ln2_b   = (const float*)d_in[8];
    const float* lin_w   = (const float*)d_in[9];
    const float* lin_b   = (const float*)d_in[10];

    float* out = (float*)d_out;

    // Pure kernel launches only — fully graph-capturable.
    pack_w_kernel<<<2 * 3 * (DD / 2), 256>>>(conv1_w, conv2_w);

    const int conv_grid = NB * (LL / TP);   // 256
    conv_ln_relu_kernel<0><<<conv_grid, 256>>>(x, conv1_b, ln1_g, ln1_b, lin_w, lin_b);
    conv_ln_relu_kernel<1><<<conv_grid, 256>>>(x, conv2_b, ln2_g, ln2_b, lin_w, lin_b);
    scan_map_kernel<<<NB, LL>>>();

    const int main_elems = NB * TT * DD;
    int tail = out_size - main_elems;
    if (tail < 0) tail = 0;
    expand_copy_kernel<<<EXP_BLOCKS, 256>>>(x, out, tail);
}